// round 10
// baseline (speedup 1.0000x reference)
#include <cuda_runtime.h>
#include <math.h>
#include <stdint.h>

#define BB   128
#define SS   512
#define HH   1024
#define FEAT 576
#define EE   512
#define XEE  64
#define BH   (BB*HH)
#define NB   129     // persistent grid size (128 GEMM blocks + 1 boundary block)

// ---------------- device scratch (static: no allocs allowed) ----------------
__device__ __align__(128) float g_X[(size_t)SS*BB*FEAT];          // [t][b][f]
__device__ __align__(128) float g_h1[BH], g_c1[BH], g_h2[BH], g_c2[BH];
__device__ __align__(128) float g_m1[BH], g_x2[BH], g_m2[BH];
__device__ __align__(128) float g_pa[2][BH], g_pb[2][BH];
__device__ __align__(128) float g_s[BB];
__device__ float g_flag;
__device__ __align__(128) float g_wx[FEAT], g_wh[HH];
__device__ float g_c0;
__device__ unsigned g_arrive;

__device__ __forceinline__ float sigm(float x) { return 1.0f/(1.0f + expf(-x)); }

// ---------------- software grid barrier (all NB blocks co-resident) ----------
__device__ __forceinline__ void grid_sync(unsigned &gen)
{
    __syncthreads();
    __threadfence();                         // release: block's writes -> L2
    gen += NB;
    if (threadIdx.x == 0) {
        atomicAdd(&g_arrive, 1u);
        while (*(volatile unsigned*)&g_arrive < gen) { __nanosleep(64); }
    }
    __syncthreads();
    __threadfence();                         // acquire: invalidate L1 (CCTL.IVALL)
}

// ---------------- collapse boundary detector: wx=Wsi^T vs, wh=Wsh^T vs ------
__global__ void prep_kernel(const float* __restrict__ Wsi, const float* __restrict__ Wsh,
                            const float* __restrict__ b_bd, const float* __restrict__ vs)
{
    int idx = blockIdx.x*256 + threadIdx.x;
    if (idx < FEAT) {
        float s = 0.f;
        for (int j = 0; j < 512; ++j) s += Wsi[(size_t)j*FEAT + idx]*vs[j];
        g_wx[idx] = s;
    } else if (idx < FEAT + HH) {
        int h = idx - FEAT;
        float s = 0.f;
        for (int j = 0; j < 512; ++j) s += Wsh[(size_t)j*HH + h]*vs[j];
        g_wh[h] = s;
    } else if (idx == FEAT + HH) {
        float s = 0.f;
        for (int j = 0; j < 512; ++j) s += b_bd[j]*vs[j];
        g_c0 = s;
    }
}

__global__ void zero_kernel()
{
    int i = blockIdx.x*256 + threadIdx.x;      // grid 512 -> BH exactly
    g_h1[i] = 0.f; g_c1[i] = 0.f; g_h2[i] = 0.f; g_c2[i] = 0.f;
    if (i == 0) g_arrive = 0u;
}

// ---------------- gather embeddings: X[t][b][f] ------------------------------
__global__ void gather_kernel(const int* __restrict__ enc, const int* __restrict__ encx,
                              const float* __restrict__ wemb, const float* __restrict__ xemb)
{
    size_t total = (size_t)SS*BB*FEAT;
    for (size_t i = (size_t)blockIdx.x*blockDim.x + threadIdx.x; i < total;
         i += (size_t)gridDim.x*blockDim.x) {
        int f  = (int)(i % FEAT);
        size_t tb = i / FEAT;
        int b = (int)(tb % BB);
        int t = (int)(tb / BB);
        float v;
        if (f < EE) v = wemb[(size_t)enc [(size_t)b*SS + t]*EE  + f];
        else        v = xemb[(size_t)encx[(size_t)b*SS + t]*XEE + (f - EE)];
        g_X[i] = v;
    }
}

// ---------------- fp32 GEMM tile: C[128, 32] += A[128,K] @ W[N,K]^T ----------
// 256 threads; thread (tm=tid>>3, tj=tid&7) owns acc[4m][4n].
// Register-prefetch double buffering over K-chunks of 32.
// GATES: smem W row r  <-> global row (r&3)*HH + nbase + (r>>2)
// else : smem W row r  <-> global row nbase + r
template<bool GATES>
__device__ __forceinline__ void gemm_tile(const float* __restrict__ A, int lda,
                                          const float* __restrict__ W, int ldw,
                                          int nbase, int kbeg, int klen,
                                          float (&acc)[4][4], float* As, float* Ws)
{
    const int tid = threadIdx.x;
    const int tm = tid >> 3, c4 = tid & 7, tj = tid & 7;
    const int nch = klen >> 5;
    const int wrow = GATES ? ((tm & 3)*HH + nbase + (tm >> 2)) : (nbase + tm);
    float4 ra[4], rw;

    {   // prefetch chunk 0
        int k0 = kbeg;
        #pragma unroll
        for (int r = 0; r < 4; ++r)
            ra[r] = *reinterpret_cast<const float4*>(A + (size_t)(tm + 32*r)*lda + k0 + c4*4);
        rw = *reinterpret_cast<const float4*>(W + (size_t)wrow*ldw + k0 + c4*4);
    }
    for (int c = 0; c < nch; ++c) {
        __syncthreads();
        #pragma unroll
        for (int r = 0; r < 4; ++r)
            *reinterpret_cast<float4*>(As + (tm + 32*r)*36 + c4*4) = ra[r];
        *reinterpret_cast<float4*>(Ws + tm*36 + c4*4) = rw;
        __syncthreads();
        if (c + 1 < nch) {
            int k0 = kbeg + ((c + 1) << 5);
            #pragma unroll
            for (int r = 0; r < 4; ++r)
                ra[r] = *reinterpret_cast<const float4*>(A + (size_t)(tm + 32*r)*lda + k0 + c4*4);
            rw = *reinterpret_cast<const float4*>(W + (size_t)wrow*ldw + k0 + c4*4);
        }
        #pragma unroll
        for (int k4 = 0; k4 < 8; ++k4) {
            float4 wv[4], av[4];
            #pragma unroll
            for (int g = 0; g < 4; ++g)
                wv[g] = *reinterpret_cast<const float4*>(Ws + (tj*4+g)*36 + k4*4);
            #pragma unroll
            for (int mi = 0; mi < 4; ++mi)
                av[mi] = *reinterpret_cast<const float4*>(As + (tm*4+mi)*36 + k4*4);
            #pragma unroll
            for (int mi = 0; mi < 4; ++mi)
                #pragma unroll
                for (int g = 0; g < 4; ++g) {
                    acc[mi][g] += av[mi].x*wv[g].x;
                    acc[mi][g] += av[mi].y*wv[g].y;
                    acc[mi][g] += av[mi].z*wv[g].z;
                    acc[mi][g] += av[mi].w*wv[g].w;
                }
        }
    }
}

// ---------------- persistent main kernel: all 512 steps ----------------------
__global__ void __launch_bounds__(256)
main_kernel(const float* __restrict__ Wmx1, const float* __restrict__ Wmh1,
            const float* __restrict__ Wih1, const float* __restrict__ Whh1,
            const float* __restrict__ b1,
            const float* __restrict__ Wmx2, const float* __restrict__ Wmh2,
            const float* __restrict__ Wih2, const float* __restrict__ Whh2,
            const float* __restrict__ b2,
            float* __restrict__ out, float* __restrict__ flags_out)
{
    __shared__ float As[128*36];
    __shared__ float Ws[32*36];
    const int tid = threadIdx.x, blk = blockIdx.x;
    const int tm = tid >> 3, tj = tid & 7;
    unsigned gen = 0;

    for (int t = 0; t < SS; ++t) {
        const float* Xt = g_X + (size_t)t*BB*FEAT;

        // ---- phase 1: m1 split-K partials + boundary detector ----
        if (blk == 128) {
            int w = tid >> 5, lane = tid & 31;
            for (int b = w; b < BB; b += 8) {
                float sum = 0.f;
                for (int k = lane; k < FEAT; k += 32) sum += Xt[(size_t)b*FEAT + k]*g_wx[k];
                for (int k = lane; k < HH;   k += 32) sum += g_h1[(size_t)b*HH + k]*g_wh[k];
                #pragma unroll
                for (int off = 16; off > 0; off >>= 1)
                    sum += __shfl_xor_sync(0xFFFFFFFFu, sum, off);
                if (lane == 0) {
                    float s = (sum + g_c0 > 0.f) ? 1.f : 0.f;
                    g_s[b] = s;
                    if (b == 0) { g_flag = s; flags_out[t] = s; }
                }
            }
        } else if (blk < 64) {                   // pa: x @ Wmx1^T, K=576 in 2x288
            int part = blk >> 5, nt = blk & 31, n0 = nt*32;
            float acc[4][4] = {};
            gemm_tile<false>(Xt, FEAT, Wmx1, FEAT, n0, part*288, 288, acc, As, Ws);
            float* dst = g_pa[part];
            #pragma unroll
            for (int mi = 0; mi < 4; ++mi)
                *reinterpret_cast<float4*>(dst + (size_t)(tm*4+mi)*HH + n0 + tj*4) =
                    make_float4(acc[mi][0], acc[mi][1], acc[mi][2], acc[mi][3]);
        } else {                                  // pb: h1 @ Wmh1^T, K=1024 in 2x512
            int q = blk - 64, part = q >> 5, nt = q & 31, n0 = nt*32;
            float acc[4][4] = {};
            gemm_tile<false>(g_h1, HH, Wmh1, HH, n0, part*512, 512, acc, As, Ws);
            float* dst = g_pb[part];
            #pragma unroll
            for (int mi = 0; mi < 4; ++mi)
                *reinterpret_cast<float4*>(dst + (size_t)(tm*4+mi)*HH + n0 + tj*4) =
                    make_float4(acc[mi][0], acc[mi][1], acc[mi][2], acc[mi][3]);
        }
        grid_sync(gen);

        // ---- phase 2: m1 = (pa0+pa1)*(pb0+pb1) ----
        for (int i = blk*256 + tid; i < BH/4; i += NB*256) {
            float4 A0 = reinterpret_cast<const float4*>(g_pa[0])[i];
            float4 A1 = reinterpret_cast<const float4*>(g_pa[1])[i];
            float4 B0 = reinterpret_cast<const float4*>(g_pb[0])[i];
            float4 B1 = reinterpret_cast<const float4*>(g_pb[1])[i];
            float4 r;
            r.x = (A0.x+A1.x)*(B0.x+B1.x);
            r.y = (A0.y+A1.y)*(B0.y+B1.y);
            r.z = (A0.z+A1.z)*(B0.z+B1.z);
            r.w = (A0.w+A1.w)*(B0.w+B1.w);
            reinterpret_cast<float4*>(g_m1)[i] = r;
        }
        grid_sync(gen);

        // ---- phase 3: gate GEMM 1 + mLSTM1 epilogue ----
        if (blk < 128) {
            int j0 = blk * 8, col = j0 + tj;
            float acc[4][4] = {};
            gemm_tile<true>(Xt,   FEAT, Wih1, FEAT, j0, 0, 576,  acc, As, Ws);
            gemm_tile<true>(g_m1, HH,   Whh1, HH,   j0, 0, 1024, acc, As, Ws);
            float bi = b1[col], bf = b1[HH+col], bg = b1[2*HH+col], bo = b1[3*HH+col];
            #pragma unroll
            for (int mi = 0; mi < 4; ++mi) {
                int m = tm*4 + mi;
                size_t idx = (size_t)m*HH + col;
                float cn = sigm(acc[mi][1]+bf)*g_c1[idx] + sigm(acc[mi][0]+bi)*tanhf(acc[mi][2]+bg);
                float hn = sigm(acc[mi][3]+bo)*tanhf(cn);
                float s  = g_s[m];
                g_x2[idx] = hn*s;
                g_h1[idx] = hn*(1.f - s);
                g_c1[idx] = cn*(1.f - s);
            }
        }
        grid_sync(gen);

        bool flag = (g_flag > 0.5f);              // uniform across all blocks

        if (flag) {
            // ---- phase 4: m2 split-K partials ----
            if (blk < 128) {
                int q = blk & 63, part = q >> 5, nt = q & 31, n0 = nt*32;
                const float* A = (blk < 64) ? g_x2 : g_h2;
                const float* W = (blk < 64) ? Wmx2 : Wmh2;
                float* dst     = (blk < 64) ? g_pa[part] : g_pb[part];
                float acc[4][4] = {};
                gemm_tile<false>(A, HH, W, HH, n0, part*512, 512, acc, As, Ws);
                #pragma unroll
                for (int mi = 0; mi < 4; ++mi)
                    *reinterpret_cast<float4*>(dst + (size_t)(tm*4+mi)*HH + n0 + tj*4) =
                        make_float4(acc[mi][0], acc[mi][1], acc[mi][2], acc[mi][3]);
            }
            grid_sync(gen);

            // ---- phase 5: m2 = (pa0+pa1)*(pb0+pb1) ----
            for (int i = blk*256 + tid; i < BH/4; i += NB*256) {
                float4 A0 = reinterpret_cast<const float4*>(g_pa[0])[i];
                float4 A1 = reinterpret_cast<const float4*>(g_pa[1])[i];
                float4 B0 = reinterpret_cast<const float4*>(g_pb[0])[i];
                float4 B1 = reinterpret_cast<const float4*>(g_pb[1])[i];
                float4 r;
                r.x = (A0.x+A1.x)*(B0.x+B1.x);
                r.y = (A0.y+A1.y)*(B0.y+B1.y);
                r.z = (A0.z+A1.z)*(B0.z+B1.z);
                r.w = (A0.w+A1.w)*(B0.w+B1.w);
                reinterpret_cast<float4*>(g_m2)[i] = r;
            }
            grid_sync(gen);
        }

        // ---- phase 6: gate GEMM 2 + conditional update + outs ----
        if (blk < 128) {
            int j0 = blk * 8, col = j0 + tj;
            if (flag) {
                float acc[4][4] = {};
                gemm_tile<true>(g_x2, HH, Wih2, HH, j0, 0, 1024, acc, As, Ws);
                gemm_tile<true>(g_m2, HH, Whh2, HH, j0, 0, 1024, acc, As, Ws);
                float bi = b2[col], bf = b2[HH+col], bg = b2[2*HH+col], bo = b2[3*HH+col];
                #pragma unroll
                for (int mi = 0; mi < 4; ++mi) {
                    int m = tm*4 + mi;
                    size_t idx = (size_t)m*HH + col;
                    float cn = sigm(acc[mi][1]+bf)*g_c2[idx] + sigm(acc[mi][0]+bi)*tanhf(acc[mi][2]+bg);
                    float hn = sigm(acc[mi][3]+bo)*tanhf(cn);
                    g_c2[idx] = cn;
                    g_h2[idx] = hn;
                    out[((size_t)m*SS + t)*HH + col] = hn;
                }
            } else {
                #pragma unroll
                for (int mi = 0; mi < 4; ++mi) {
                    int m = tm*4 + mi;
                    out[((size_t)m*SS + t)*HH + col] = g_h2[(size_t)m*HH + col];
                }
            }
        }
        grid_sync(gen);
    }

    // ---- final state outputs ----
    size_t off1 = (size_t)BB*SS*HH;
    for (int i = blk*256 + tid; i < BH; i += NB*256) {
        out[off1 + i]      = g_h2[i];
        out[off1 + BH + i] = g_c2[i];
    }
}

extern "C" void kernel_launch(void* const* d_in, const int* in_sizes, int n_in,
                              void* d_out, int out_size)
{
    const int*   enc  = (const int*)d_in[0];
    const int*   encx = (const int*)d_in[1];
    const float* wemb = (const float*)d_in[2];
    const float* xemb = (const float*)d_in[3];
    const float* Wsi  = (const float*)d_in[4];
    const float* Wsh  = (const float*)d_in[5];
    const float* b_bd = (const float*)d_in[6];
    const float* vs   = (const float*)d_in[7];
    const float* Wmx1 = (const float*)d_in[8];
    const float* Wmh1 = (const float*)d_in[9];
    const float* Wih1 = (const float*)d_in[10];
    const float* Whh1 = (const float*)d_in[11];
    const float* b1   = (const float*)d_in[12];
    const float* Wmx2 = (const float*)d_in[13];
    const float* Wmh2 = (const float*)d_in[14];
    const float* Wih2 = (const float*)d_in[15];
    const float* Whh2 = (const float*)d_in[16];
    const float* b2   = (const float*)d_in[17];
    float* out = (float*)d_out;
    size_t off1 = (size_t)BB*SS*HH;
    float* flags_ptr = out + off1 + 2*(size_t)BH;

    prep_kernel<<<7, 256>>>(Wsi, Wsh, b_bd, vs);
    zero_kernel<<<512, 256>>>();
    gather_kernel<<<2048, 256>>>(enc, encx, wemb, xemb);
    main_kernel<<<NB, 256>>>(Wmx1, Wmh1, Wih1, Whh1, b1,
                             Wmx2, Wmh2, Wih2, Whh2, b2, out, flags_ptr);
}

// round 12
// speedup vs baseline: 2.2055x; 2.2055x over previous
#include <cuda_runtime.h>
#include <math.h>
#include <stdint.h>

#define BB   128
#define SS   512
#define HH   1024
#define FEAT 576
#define EE   512
#define XEE  64
#define BH   (BB*HH)
#define NB   129
#define K1A  1600          // FEAT + HH
#define K2A  2048          // HH + HH
#define NG   4096          // 4*HH

// ---------------- device scratch ----------------
__device__ __align__(128) float g_X[(size_t)SS*BB*FEAT];
__device__ __align__(128) float g_W1[(size_t)NG*K1A];     // [Wih1|Whh1] rows x k
__device__ __align__(128) float g_W2[(size_t)NG*K2A];     // [Wih2|Whh2]
__device__ __align__(128) float g_cat1[BB*K1A];           // [x | m1]
__device__ __align__(128) float g_cat2[BB*K2A];           // [x2 | m2]
__device__ __align__(128) float g_h1[BH], g_c1[BH], g_h2[BH], g_c2[BH];
__device__ __align__(128) float g_ppa[8][BH], g_ppb[8][BH];
__device__ __align__(128) float g_pz[4][BB*NG];
__device__ __align__(128) float g_s[BB];
__device__ float g_flag;
__device__ __align__(128) float g_wx[FEAT], g_wh[HH];
__device__ float g_c0;
__device__ unsigned g_arrive;

__device__ __forceinline__ float sigm(float x) { return 1.0f/(1.0f + expf(-x)); }

__device__ __forceinline__ void grid_sync(unsigned &gen)
{
    __syncthreads();
    __threadfence();
    gen += NB;
    if (threadIdx.x == 0) {
        atomicAdd(&g_arrive, 1u);
        while (*(volatile unsigned*)&g_arrive < gen) { __nanosleep(64); }
    }
    __syncthreads();
    __threadfence();
}

// ---------------- prep kernels ----------------
__global__ void prep_kernel(const float* __restrict__ Wsi, const float* __restrict__ Wsh,
                            const float* __restrict__ b_bd, const float* __restrict__ vs)
{
    int idx = blockIdx.x*256 + threadIdx.x;
    if (idx < FEAT) {
        float s = 0.f;
        for (int j = 0; j < 512; ++j) s += Wsi[(size_t)j*FEAT + idx]*vs[j];
        g_wx[idx] = s;
    } else if (idx < FEAT + HH) {
        int h = idx - FEAT;
        float s = 0.f;
        for (int j = 0; j < 512; ++j) s += Wsh[(size_t)j*HH + h]*vs[j];
        g_wh[h] = s;
    } else if (idx == FEAT + HH) {
        float s = 0.f;
        for (int j = 0; j < 512; ++j) s += b_bd[j]*vs[j];
        g_c0 = s;
    }
}

__global__ void prep2_kernel(const float* __restrict__ Wih1, const float* __restrict__ Whh1,
                             const float* __restrict__ Wih2, const float* __restrict__ Whh2)
{
    size_t n1 = (size_t)NG*K1A, n2 = (size_t)NG*K2A;
    for (size_t i = (size_t)blockIdx.x*blockDim.x + threadIdx.x; i < n1 + n2;
         i += (size_t)gridDim.x*blockDim.x) {
        if (i < n1) {
            int n = (int)(i / K1A), k = (int)(i % K1A);
            g_W1[i] = (k < FEAT) ? Wih1[(size_t)n*FEAT + k] : Whh1[(size_t)n*HH + (k-FEAT)];
        } else {
            size_t j = i - n1;
            int n = (int)(j / K2A), k = (int)(j % K2A);
            g_W2[j] = (k < HH) ? Wih2[(size_t)n*HH + k] : Whh2[(size_t)n*HH + (k-HH)];
        }
    }
}

__global__ void zero_kernel()
{
    int i = blockIdx.x*256 + threadIdx.x;
    g_h1[i] = 0.f; g_c1[i] = 0.f; g_h2[i] = 0.f; g_c2[i] = 0.f;
    if (i == 0) g_arrive = 0u;
}

__global__ void gather_kernel(const int* __restrict__ enc, const int* __restrict__ encx,
                              const float* __restrict__ wemb, const float* __restrict__ xemb)
{
    size_t total = (size_t)SS*BB*FEAT;
    for (size_t i = (size_t)blockIdx.x*blockDim.x + threadIdx.x; i < total;
         i += (size_t)gridDim.x*blockDim.x) {
        int f  = (int)(i % FEAT);
        size_t tb = i / FEAT;
        int b = (int)(tb % BB);
        int t = (int)(tb / BB);
        float v;
        if (f < EE) v = wemb[(size_t)enc [(size_t)b*SS + t]*EE  + f];
        else        v = xemb[(size_t)encx[(size_t)b*SS + t]*XEE + (f - EE)];
        g_X[i] = v;
    }
}

// ---------------- 128x128 GEMM tile, 8x8/thread, k-major smem ----------------
// C[128,128] += A[128, k-range] @ W[rows, k-range]^T   (W pre-offset to row n0,
// C pre-offset to col j0). 256 threads. Chunks of 16 k, register prefetch.
#define LDS_K 132
__device__ __forceinline__ void rank1(float4 (&acc)[4], float4 a, float4 w)
{
    acc[0].x += a.x*w.x; acc[0].y += a.x*w.y; acc[0].z += a.x*w.z; acc[0].w += a.x*w.w;
    acc[1].x += a.y*w.x; acc[1].y += a.y*w.y; acc[1].z += a.y*w.z; acc[1].w += a.y*w.w;
    acc[2].x += a.z*w.x; acc[2].y += a.z*w.y; acc[2].z += a.z*w.z; acc[2].w += a.z*w.w;
    acc[3].x += a.w*w.x; acc[3].y += a.w*w.y; acc[3].z += a.w*w.z; acc[3].w += a.w*w.w;
}

__device__ __forceinline__ void gemm128(const float* __restrict__ A, int lda,
                                        const float* __restrict__ W, int ldw,
                                        float* __restrict__ C, int ldc,
                                        int kbeg, int nch,
                                        float* __restrict__ As, float* __restrict__ Ws)
{
    const int tid = threadIdx.x;
    const int tx4 = (tid & 15) * 4, ty4 = (tid >> 4) * 4;
    const int m0 = tid >> 2, k40 = tid & 3;
    const int m1 = m0 + 64;
    const int kb = k40 * 4;

    float4 acc[2][2][4];
    #pragma unroll
    for (int h = 0; h < 2; ++h)
        #pragma unroll
        for (int g = 0; g < 2; ++g)
            #pragma unroll
            for (int i = 0; i < 4; ++i) acc[h][g][i] = make_float4(0.f,0.f,0.f,0.f);

    const float* Ap0 = A + (size_t)m0*lda + kbeg + kb;
    const float* Ap1 = A + (size_t)m1*lda + kbeg + kb;
    const float* Wp0 = W + (size_t)m0*ldw + kbeg + kb;
    const float* Wp1 = W + (size_t)m1*ldw + kbeg + kb;

    float4 ra0 = *(const float4*)Ap0, ra1 = *(const float4*)Ap1;
    float4 rw0 = *(const float4*)Wp0, rw1 = *(const float4*)Wp1;

    for (int c = 0; c < nch; ++c) {
        __syncthreads();
        As[(kb+0)*LDS_K + m0] = ra0.x; As[(kb+1)*LDS_K + m0] = ra0.y;
        As[(kb+2)*LDS_K + m0] = ra0.z; As[(kb+3)*LDS_K + m0] = ra0.w;
        As[(kb+0)*LDS_K + m1] = ra1.x; As[(kb+1)*LDS_K + m1] = ra1.y;
        As[(kb+2)*LDS_K + m1] = ra1.z; As[(kb+3)*LDS_K + m1] = ra1.w;
        Ws[(kb+0)*LDS_K + m0] = rw0.x; Ws[(kb+1)*LDS_K + m0] = rw0.y;
        Ws[(kb+2)*LDS_K + m0] = rw0.z; Ws[(kb+3)*LDS_K + m0] = rw0.w;
        Ws[(kb+0)*LDS_K + m1] = rw1.x; Ws[(kb+1)*LDS_K + m1] = rw1.y;
        Ws[(kb+2)*LDS_K + m1] = rw1.z; Ws[(kb+3)*LDS_K + m1] = rw1.w;
        __syncthreads();
        if (c + 1 < nch) {
            int o = (c + 1) * 16;
            ra0 = *(const float4*)(Ap0 + o); ra1 = *(const float4*)(Ap1 + o);
            rw0 = *(const float4*)(Wp0 + o); rw1 = *(const float4*)(Wp1 + o);
        }
        #pragma unroll
        for (int k = 0; k < 16; ++k) {
            float4 a0 = *(const float4*)(As + k*LDS_K + ty4);
            float4 a1 = *(const float4*)(As + k*LDS_K + ty4 + 64);
            float4 w0 = *(const float4*)(Ws + k*LDS_K + tx4);
            float4 w1 = *(const float4*)(Ws + k*LDS_K + tx4 + 64);
            rank1(acc[0][0], a0, w0); rank1(acc[0][1], a0, w1);
            rank1(acc[1][0], a1, w0); rank1(acc[1][1], a1, w1);
        }
    }
    #pragma unroll
    for (int h = 0; h < 2; ++h)
        #pragma unroll
        for (int i = 0; i < 4; ++i) {
            int row = ty4 + i + h*64;
            *(float4*)(C + (size_t)row*ldc + tx4)      = acc[h][0][i];
            *(float4*)(C + (size_t)row*ldc + tx4 + 64) = acc[h][1][i];
        }
}

// ---------------- persistent main kernel ----------------
__global__ void __launch_bounds__(256, 1)
main_kernel(const float* __restrict__ Wmx1, const float* __restrict__ Wmh1,
            const float* __restrict__ b1,
            const float* __restrict__ Wmx2, const float* __restrict__ Wmh2,
            const float* __restrict__ b2,
            float* __restrict__ out, float* __restrict__ flags_out)
{
    __shared__ float As[16*LDS_K];
    __shared__ float Ws[16*LDS_K];
    const int tid = threadIdx.x, blk = blockIdx.x;
    unsigned gen = 0;

    for (int t = 0; t < SS; ++t) {
        const float* Xt = g_X + (size_t)t*BB*FEAT;

        // ---- P1: m1 partials (pa: x@Wmx1^T, pb: h1@Wmh1^T) + boundary ----
        if (blk == 128) {
            int w = tid >> 5, lane = tid & 31;
            for (int b = w; b < BB; b += 8) {
                float sum = 0.f;
                for (int k = lane; k < FEAT; k += 32) sum += Xt[(size_t)b*FEAT + k]*g_wx[k];
                for (int k = lane; k < HH;   k += 32) sum += g_h1[(size_t)b*HH + k]*g_wh[k];
                #pragma unroll
                for (int off = 16; off > 0; off >>= 1)
                    sum += __shfl_xor_sync(0xFFFFFFFFu, sum, off);
                if (lane == 0) {
                    float s = (sum + g_c0 > 0.f) ? 1.f : 0.f;
                    g_s[b] = s;
                    if (b == 0) { g_flag = s; flags_out[t] = s; }
                }
            }
        } else if (blk < 64) {                 // pa: K=576, splits {80,80,80,80,64,64,64,64}
            int nt = blk >> 3, sp = blk & 7;
            int kbeg = (sp < 4) ? 80*sp : 320 + 64*(sp-4);
            int nch  = (sp < 4) ? 5 : 4;
            gemm128(Xt, FEAT, Wmx1 + (size_t)(nt*128)*FEAT, FEAT,
                    g_ppa[sp] + nt*128, HH, kbeg, nch, As, Ws);
        } else {                               // pb: K=1024, 8 splits of 128
            int q = blk - 64, nt = q >> 3, sp = q & 7;
            gemm128(g_h1, HH, Wmh1 + (size_t)(nt*128)*HH, HH,
                    g_ppb[sp] + nt*128, HH, sp*128, 8, As, Ws);
        }
        grid_sync(gen);

        // ---- P2: m1 = (sum pa)(sum pb) -> cat1[:,576:]; copy Xt -> cat1[:,:576] ----
        for (int i = blk*256 + tid; i < BH/4; i += NB*256) {
            int m = i >> 8, c4 = (i & 255) * 4;
            float4 a = make_float4(0,0,0,0), b = make_float4(0,0,0,0);
            #pragma unroll
            for (int s = 0; s < 8; ++s) {
                float4 pa = *(const float4*)(g_ppa[s] + (size_t)m*HH + c4);
                float4 pb = *(const float4*)(g_ppb[s] + (size_t)m*HH + c4);
                a.x += pa.x; a.y += pa.y; a.z += pa.z; a.w += pa.w;
                b.x += pb.x; b.y += pb.y; b.z += pb.z; b.w += pb.w;
            }
            *(float4*)(g_cat1 + (size_t)m*K1A + FEAT + c4) =
                make_float4(a.x*b.x, a.y*b.y, a.z*b.z, a.w*b.w);
        }
        for (int i = blk*256 + tid; i < BB*FEAT/4; i += NB*256) {
            int m = i / 144, c4 = (i % 144) * 4;
            *(float4*)(g_cat1 + (size_t)m*K1A + c4) = *(const float4*)(Xt + (size_t)m*FEAT + c4);
        }
        grid_sync(gen);

        // ---- P3: z1 partials: cat1[128,1600] @ W1[4096,1600]^T, 32nt x 4 splits ----
        if (blk < 128) {
            int nt = blk >> 2, sp = blk & 3;
            gemm128(g_cat1, K1A, g_W1 + (size_t)(nt*128)*K1A, K1A,
                    g_pz[sp] + nt*128, NG, sp*400, 25, As, Ws);
        }
        grid_sync(gen);

        bool flag = (*(volatile float*)&g_flag > 0.5f);

        // ---- P3b: gates 1 epilogue: h1,c1,x2; out copy when !flag ----
        for (int i = blk*256 + tid; i < BH/4; i += NB*256) {
            int m = i >> 8, c4 = (i & 255) * 4;
            float4 z[4];
            #pragma unroll
            for (int g = 0; g < 4; ++g) {
                int col = g*HH + c4;
                float4 sum = *(const float4*)(b1 + col);
                #pragma unroll
                for (int s = 0; s < 4; ++s) {
                    float4 p = *(const float4*)(g_pz[s] + (size_t)m*NG + col);
                    sum.x += p.x; sum.y += p.y; sum.z += p.z; sum.w += p.w;
                }
                z[g] = sum;
            }
            float s = g_s[m];
            size_t idx = (size_t)m*HH + c4;
            float4 co = *(const float4*)(g_c1 + idx);
            float cn0 = sigm(z[1].x)*co.x + sigm(z[0].x)*tanhf(z[2].x);
            float cn1 = sigm(z[1].y)*co.y + sigm(z[0].y)*tanhf(z[2].y);
            float cn2 = sigm(z[1].z)*co.z + sigm(z[0].z)*tanhf(z[2].z);
            float cn3 = sigm(z[1].w)*co.w + sigm(z[0].w)*tanhf(z[2].w);
            float hn0 = sigm(z[3].x)*tanhf(cn0);
            float hn1 = sigm(z[3].y)*tanhf(cn1);
            float hn2 = sigm(z[3].z)*tanhf(cn2);
            float hn3 = sigm(z[3].w)*tanhf(cn3);
            *(float4*)(g_cat2 + (size_t)m*K2A + c4) = make_float4(hn0*s, hn1*s, hn2*s, hn3*s);
            float r = 1.f - s;
            *(float4*)(g_h1 + idx) = make_float4(hn0*r, hn1*r, hn2*r, hn3*r);
            *(float4*)(g_c1 + idx) = make_float4(cn0*r, cn1*r, cn2*r, cn3*r);
            if (!flag)
                *(float4*)(out + ((size_t)m*SS + t)*HH + c4) = *(const float4*)(g_h2 + idx);
        }
        grid_sync(gen);

        if (flag) {
            // ---- P4: m2 partials (pa: x2@Wmx2^T, pb: h2@Wmh2^T), K=1024 ----
            if (blk < 64) {
                int nt = blk >> 3, sp = blk & 7;
                gemm128(g_cat2, K2A, Wmx2 + (size_t)(nt*128)*HH, HH,
                        g_ppa[sp] + nt*128, HH, sp*128, 8, As, Ws);
            } else if (blk < 128) {
                int q = blk - 64, nt = q >> 3, sp = q & 7;
                gemm128(g_h2, HH, Wmh2 + (size_t)(nt*128)*HH, HH,
                        g_ppb[sp] + nt*128, HH, sp*128, 8, As, Ws);
            }
            grid_sync(gen);

            // ---- P5: m2 -> cat2[:,1024:] ----
            for (int i = blk*256 + tid; i < BH/4; i += NB*256) {
                int m = i >> 8, c4 = (i & 255) * 4;
                float4 a = make_float4(0,0,0,0), b = make_float4(0,0,0,0);
                #pragma unroll
                for (int s = 0; s < 8; ++s) {
                    float4 pa = *(const float4*)(g_ppa[s] + (size_t)m*HH + c4);
                    float4 pb = *(const float4*)(g_ppb[s] + (size_t)m*HH + c4);
                    a.x += pa.x; a.y += pa.y; a.z += pa.z; a.w += pa.w;
                    b.x += pb.x; b.y += pb.y; b.z += pb.z; b.w += pb.w;
                }
                *(float4*)(g_cat2 + (size_t)m*K2A + HH + c4) =
                    make_float4(a.x*b.x, a.y*b.y, a.z*b.z, a.w*b.w);
            }
            grid_sync(gen);

            // ---- P6: z2 partials: cat2[128,2048] @ W2^T ----
            if (blk < 128) {
                int nt = blk >> 2, sp = blk & 3;
                gemm128(g_cat2, K2A, g_W2 + (size_t)(nt*128)*K2A, K2A,
                        g_pz[sp] + nt*128, NG, sp*512, 32, As, Ws);
            }
            grid_sync(gen);

            // ---- P6b: gates 2 epilogue: h2,c2,out ----
            for (int i = blk*256 + tid; i < BH/4; i += NB*256) {
                int m = i >> 8, c4 = (i & 255) * 4;
                float4 z[4];
                #pragma unroll
                for (int g = 0; g < 4; ++g) {
                    int col = g*HH + c4;
                    float4 sum = *(const float4*)(b2 + col);
                    #pragma unroll
                    for (int s = 0; s < 4; ++s) {
                        float4 p = *(const float4*)(g_pz[s] + (size_t)m*NG + col);
                        sum.x += p.x; sum.y += p.y; sum.z += p.z; sum.w += p.w;
                    }
                    z[g] = sum;
                }
                size_t idx = (size_t)m*HH + c4;
                float4 co = *(const float4*)(g_c2 + idx);
                float cn0 = sigm(z[1].x)*co.x + sigm(z[0].x)*tanhf(z[2].x);
                float cn1 = sigm(z[1].y)*co.y + sigm(z[0].y)*tanhf(z[2].y);
                float cn2 = sigm(z[1].z)*co.z + sigm(z[0].z)*tanhf(z[2].z);
                float cn3 = sigm(z[1].w)*co.w + sigm(z[0].w)*tanhf(z[2].w);
                float hn0 = sigm(z[3].x)*tanhf(cn0);
                float hn1 = sigm(z[3].y)*tanhf(cn1);
                float hn2 = sigm(z[3].z)*tanhf(cn2);
                float hn3 = sigm(z[3].w)*tanhf(cn3);
                *(float4*)(g_c2 + idx) = make_float4(cn0, cn1, cn2, cn3);
                *(float4*)(g_h2 + idx) = make_float4(hn0, hn1, hn2, hn3);
                *(float4*)(out + ((size_t)m*SS + t)*HH + c4) = make_float4(hn0, hn1, hn2, hn3);
            }
            grid_sync(gen);
        }
    }

    size_t off1 = (size_t)BB*SS*HH;
    for (int i = blk*256 + tid; i < BH; i += NB*256) {
        out[off1 + i]      = g_h2[i];
        out[off1 + BH + i] = g_c2[i];
    }
}

extern "C" void kernel_launch(void* const* d_in, const int* in_sizes, int n_in,
                              void* d_out, int out_size)
{
    const int*   enc  = (const int*)d_in[0];
    const int*   encx = (const int*)d_in[1];
    const float* wemb = (const float*)d_in[2];
    const float* xemb = (const float*)d_in[3];
    const float* Wsi  = (const float*)d_in[4];
    const float* Wsh  = (const float*)d_in[5];
    const float* b_bd = (const float*)d_in[6];
    const float* vs   = (const float*)d_in[7];
    const float* Wmx1 = (const float*)d_in[8];
    const float* Wmh1 = (const float*)d_in[9];
    const float* Wih1 = (const float*)d_in[10];
    const float* Whh1 = (const float*)d_in[11];
    const float* b1   = (const float*)d_in[12];
    const float* Wmx2 = (const float*)d_in[13];
    const float* Wmh2 = (const float*)d_in[14];
    const float* Wih2 = (const float*)d_in[15];
    const float* Whh2 = (const float*)d_in[16];
    const float* b2   = (const float*)d_in[17];
    float* out = (float*)d_out;
    size_t off1 = (size_t)BB*SS*HH;
    float* flags_ptr = out + off1 + 2*(size_t)BH;

    prep_kernel <<<7, 256>>>(Wsi, Wsh, b_bd, vs);
    prep2_kernel<<<4096, 256>>>(Wih1, Whh1, Wih2, Whh2);
    zero_kernel <<<512, 256>>>();
    gather_kernel<<<2048, 256>>>(enc, encx, wemb, xemb);
    main_kernel <<<NB, 256>>>(Wmx1, Wmh1, b1, Wmx2, Wmh2, b2, out, flags_ptr);
}

// round 15
// speedup vs baseline: 3.3346x; 1.5119x over previous
#include <cuda_runtime.h>
#include <math.h>
#include <stdint.h>

#define BB   128
#define SS   512
#define HH   1024
#define FEAT 576
#define EE   512
#define XEE  64
#define BH   (BB*HH)
#define NB   129
#define K1A  1600
#define K2A  2048
#define NG   4096
#define SA   36                          // smem row stride (floats)
#define SMEM_DYN (4*128*SA*4)            // Ahi,Alo,Whi,Wlo = 73728 B

// ---------------- device scratch ----------------
__device__ __align__(128) float g_X[(size_t)SS*BB*FEAT];
__device__ __align__(128) float g_W1[(size_t)NG*K1A];
__device__ __align__(128) float g_W2[(size_t)NG*K2A];
__device__ __align__(128) float g_cat1[BB*K1A];
__device__ __align__(128) float g_cat2[BB*K2A];
__device__ __align__(128) float g_h1[BH], g_c1[BH], g_h2[BH], g_c2[BH];
__device__ __align__(128) float g_ppa[8][BH], g_ppb[8][BH];
__device__ __align__(128) float g_pz[4][BB*NG];
__device__ __align__(128) float g_s[BB];
__device__ float g_flag;
__device__ __align__(128) float g_wx[FEAT], g_wh[HH];
__device__ float g_c0;
__device__ unsigned g_arrive;

__device__ __forceinline__ float sigm(float x) { return 1.0f/(1.0f + expf(-x)); }
__device__ __forceinline__ uint32_t f2b(float x) { return __float_as_uint(x); }
__device__ __forceinline__ float hi_tf32(float x) {
    return __uint_as_float(__float_as_uint(x) & 0xFFFFE000u);
}
__device__ __forceinline__ float rna_tf32(float x) {
    uint32_t u; asm("cvt.rna.tf32.f32 %0, %1;" : "=r"(u) : "f"(x));
    return __uint_as_float(u);
}

__device__ __forceinline__ void mma_tf32(float (&d)[4], const uint32_t (&a)[4],
                                         const uint32_t (&b)[2])
{
    asm volatile(
        "mma.sync.aligned.m16n8k8.row.col.f32.tf32.tf32.f32 "
        "{%0,%1,%2,%3}, {%4,%5,%6,%7}, {%8,%9}, {%0,%1,%2,%3};"
        : "+f"(d[0]), "+f"(d[1]), "+f"(d[2]), "+f"(d[3])
        : "r"(a[0]), "r"(a[1]), "r"(a[2]), "r"(a[3]), "r"(b[0]), "r"(b[1]));
}

__device__ __forceinline__ void grid_sync(unsigned &gen)
{
    __syncthreads();
    __threadfence();
    gen += NB;
    if (threadIdx.x == 0) {
        atomicAdd(&g_arrive, 1u);
        while (*(volatile unsigned*)&g_arrive < gen) { __nanosleep(64); }
    }
    __syncthreads();
    __threadfence();
}

// ---------------- prep kernels ----------------
__global__ void prep_kernel(const float* __restrict__ Wsi, const float* __restrict__ Wsh,
                            const float* __restrict__ b_bd, const float* __restrict__ vs)
{
    int idx = blockIdx.x*256 + threadIdx.x;
    if (idx < FEAT) {
        float s = 0.f;
        for (int j = 0; j < 512; ++j) s += Wsi[(size_t)j*FEAT + idx]*vs[j];
        g_wx[idx] = s;
    } else if (idx < FEAT + HH) {
        int h = idx - FEAT;
        float s = 0.f;
        for (int j = 0; j < 512; ++j) s += Wsh[(size_t)j*HH + h]*vs[j];
        g_wh[h] = s;
    } else if (idx == FEAT + HH) {
        float s = 0.f;
        for (int j = 0; j < 512; ++j) s += b_bd[j]*vs[j];
        g_c0 = s;
    }
}

__global__ void prep2_kernel(const float* __restrict__ Wih1, const float* __restrict__ Whh1,
                             const float* __restrict__ Wih2, const float* __restrict__ Whh2)
{
    size_t n1 = (size_t)NG*K1A, n2 = (size_t)NG*K2A;
    for (size_t i = (size_t)blockIdx.x*blockDim.x + threadIdx.x; i < n1 + n2;
         i += (size_t)gridDim.x*blockDim.x) {
        if (i < n1) {
            int n = (int)(i / K1A), k = (int)(i % K1A);
            g_W1[i] = (k < FEAT) ? Wih1[(size_t)n*FEAT + k] : Whh1[(size_t)n*HH + (k-FEAT)];
        } else {
            size_t j = i - n1;
            int n = (int)(j / K2A), k = (int)(j % K2A);
            g_W2[j] = (k < HH) ? Wih2[(size_t)n*HH + k] : Whh2[(size_t)n*HH + (k-HH)];
        }
    }
}

__global__ void zero_kernel()
{
    int i = blockIdx.x*256 + threadIdx.x;
    g_h1[i] = 0.f; g_c1[i] = 0.f; g_h2[i] = 0.f; g_c2[i] = 0.f;
    if (i == 0) g_arrive = 0u;
}

__global__ void gather_kernel(const int* __restrict__ enc, const int* __restrict__ encx,
                              const float* __restrict__ wemb, const float* __restrict__ xemb)
{
    size_t total = (size_t)SS*BB*FEAT;
    for (size_t i = (size_t)blockIdx.x*blockDim.x + threadIdx.x; i < total;
         i += (size_t)gridDim.x*blockDim.x) {
        int f  = (int)(i % FEAT);
        size_t tb = i / FEAT;
        int b = (int)(tb % BB);
        int t = (int)(tb / BB);
        float v;
        if (f < EE) v = wemb[(size_t)enc [(size_t)b*SS + t]*EE  + f];
        else        v = xemb[(size_t)encx[(size_t)b*SS + t]*XEE + (f - EE)];
        g_X[i] = v;
    }
}

// ---------------- tensor-core GEMM via mma.sync (tf32 x3 split) --------------
// C[128,128] = A[128,Kr] @ W[128 rows,Kr]^T.  256 threads = 8 warps (4m x 2n),
// warp tile 32x64 (2 x 8 m16n8k8 fragments, 3 MMAs each for the error split).
// K-chunks of 32: each thread stages 4 float4 of A and 4 of W (full 128x32).
__device__ void tc_gemm(const float* __restrict__ A, int lda,
                        const float* __restrict__ W, int ldw,
                        float* __restrict__ C, int ldc,
                        int kbeg, int nch, float* __restrict__ sm)
{
    float* Ahi = sm;
    float* Alo = sm + 128*SA;
    float* Whi = sm + 2*128*SA;
    float* Wlo = sm + 3*128*SA;
    const int tid = threadIdx.x;
    const int warp = tid >> 5, lane = tid & 31;
    const int wm = (warp & 3) * 32, wn = (warp >> 2) * 64;
    const int grp = lane >> 2, tig = lane & 3;
    const int lrow = tid >> 3, lkc = (tid & 7) * 4;      // staging coords (rows 0..31 +32r)

    float acc[2][8][4];
    #pragma unroll
    for (int mi = 0; mi < 2; ++mi)
        #pragma unroll
        for (int ni = 0; ni < 8; ++ni)
            #pragma unroll
            for (int q = 0; q < 4; ++q) acc[mi][ni][q] = 0.f;

    const float* Ap = A + (size_t)lrow*lda + kbeg + lkc;
    const float* Wp = W + (size_t)lrow*ldw + kbeg + lkc;
    float4 ra[4], rw[4];
    #pragma unroll
    for (int r = 0; r < 4; ++r) {
        ra[r] = *(const float4*)(Ap + (size_t)(32*r)*lda);
        rw[r] = *(const float4*)(Wp + (size_t)(32*r)*ldw);
    }

    for (int c = 0; c < nch; ++c) {
        __syncthreads();
        #pragma unroll
        for (int r = 0; r < 4; ++r) {
            int row = lrow + 32*r;
            float4 hi, lo;
            hi.x = hi_tf32(ra[r].x); lo.x = rna_tf32(ra[r].x - hi.x);
            hi.y = hi_tf32(ra[r].y); lo.y = rna_tf32(ra[r].y - hi.y);
            hi.z = hi_tf32(ra[r].z); lo.z = rna_tf32(ra[r].z - hi.z);
            hi.w = hi_tf32(ra[r].w); lo.w = rna_tf32(ra[r].w - hi.w);
            *(float4*)(Ahi + row*SA + lkc) = hi;
            *(float4*)(Alo + row*SA + lkc) = lo;
            hi.x = hi_tf32(rw[r].x); lo.x = rna_tf32(rw[r].x - hi.x);
            hi.y = hi_tf32(rw[r].y); lo.y = rna_tf32(rw[r].y - hi.y);
            hi.z = hi_tf32(rw[r].z); lo.z = rna_tf32(rw[r].z - hi.z);
            hi.w = hi_tf32(rw[r].w); lo.w = rna_tf32(rw[r].w - hi.w);
            *(float4*)(Whi + row*SA + lkc) = hi;
            *(float4*)(Wlo + row*SA + lkc) = lo;
        }
        __syncthreads();
        if (c + 1 < nch) {
            #pragma unroll
            for (int r = 0; r < 4; ++r) {
                ra[r] = *(const float4*)(Ap + (size_t)(32*r)*lda + (c + 1)*32);
                rw[r] = *(const float4*)(Wp + (size_t)(32*r)*ldw + (c + 1)*32);
            }
        }
        #pragma unroll
        for (int k8 = 0; k8 < 4; ++k8) {
            const int kb = k8*8 + tig;
            uint32_t ah[2][4], al[2][4];
            #pragma unroll
            for (int mi = 0; mi < 2; ++mi) {
                int r0 = wm + mi*16 + grp;
                ah[mi][0] = f2b(Ahi[r0*SA + kb]);
                ah[mi][1] = f2b(Ahi[(r0+8)*SA + kb]);
                ah[mi][2] = f2b(Ahi[r0*SA + kb + 4]);
                ah[mi][3] = f2b(Ahi[(r0+8)*SA + kb + 4]);
                al[mi][0] = f2b(Alo[r0*SA + kb]);
                al[mi][1] = f2b(Alo[(r0+8)*SA + kb]);
                al[mi][2] = f2b(Alo[r0*SA + kb + 4]);
                al[mi][3] = f2b(Alo[(r0+8)*SA + kb + 4]);
            }
            #pragma unroll
            for (int ni = 0; ni < 8; ++ni) {
                int n0 = wn + ni*8 + grp;
                uint32_t wh[2] = { f2b(Whi[n0*SA + kb]), f2b(Whi[n0*SA + kb + 4]) };
                uint32_t wl[2] = { f2b(Wlo[n0*SA + kb]), f2b(Wlo[n0*SA + kb + 4]) };
                #pragma unroll
                for (int mi = 0; mi < 2; ++mi) {
                    mma_tf32(acc[mi][ni], ah[mi], wh);
                    mma_tf32(acc[mi][ni], al[mi], wh);
                    mma_tf32(acc[mi][ni], ah[mi], wl);
                }
            }
        }
    }
    #pragma unroll
    for (int mi = 0; mi < 2; ++mi)
        #pragma unroll
        for (int ni = 0; ni < 8; ++ni) {
            int row = wm + mi*16 + grp;
            int col = wn + ni*8 + 2*tig;
            *(float2*)(C + (size_t)row*ldc + col)     = make_float2(acc[mi][ni][0], acc[mi][ni][1]);
            *(float2*)(C + (size_t)(row+8)*ldc + col) = make_float2(acc[mi][ni][2], acc[mi][ni][3]);
        }
}

// ---------------- persistent main kernel ----------------
__global__ void __launch_bounds__(256)
main_kernel(const float* __restrict__ Wmx1, const float* __restrict__ Wmh1,
            const float* __restrict__ b1,
            const float* __restrict__ Wmx2, const float* __restrict__ Wmh2,
            const float* __restrict__ b2,
            float* __restrict__ out, float* __restrict__ flags_out)
{
    extern __shared__ float smf[];
    const int tid = threadIdx.x, blk = blockIdx.x;
    unsigned gen = 0;

    for (int t = 0; t < SS; ++t) {
        const float* Xt = g_X + (size_t)t*BB*FEAT;

        // ---- P1: m1 partials + boundary detector ----
        if (blk == 128) {
            int w = tid >> 5, lane = tid & 31;
            for (int b = w; b < BB; b += 8) {
                float sum = 0.f;
                for (int k = lane; k < FEAT; k += 32) sum += Xt[(size_t)b*FEAT + k]*g_wx[k];
                for (int k = lane; k < HH;   k += 32) sum += g_h1[(size_t)b*HH + k]*g_wh[k];
                #pragma unroll
                for (int off = 16; off > 0; off >>= 1)
                    sum += __shfl_xor_sync(0xFFFFFFFFu, sum, off);
                if (lane == 0) {
                    float s = (sum + g_c0 > 0.f) ? 1.f : 0.f;
                    g_s[b] = s;
                    if (b == 0) { g_flag = s; flags_out[t] = s; }
                }
            }
        } else if (blk < 32) {                 // pa: x@Wmx1^T, K=576, 4 splits {5,5,4,4}ch
            int nt = blk >> 2, sp = blk & 3;
            int kbeg = (sp < 2) ? sp*160 : 320 + (sp-2)*128;
            int nch  = 5 - (sp >> 1);
            tc_gemm(Xt, FEAT, Wmx1 + (size_t)(nt*128)*FEAT, FEAT,
                    g_ppa[sp] + nt*128, HH, kbeg, nch, smf);
        } else if (blk < 96) {                 // pb: h1@Wmh1^T, K=1024, 8 splits x4ch
            int q = blk - 32, nt = q >> 3, sp = q & 7;
            tc_gemm(g_h1, HH, Wmh1 + (size_t)(nt*128)*HH, HH,
                    g_ppb[sp] + nt*128, HH, sp*128, 4, smf);
        }
        grid_sync(gen);

        // ---- P2: m1 -> cat1[:,576:]; Xt -> cat1[:,:576] ----
        for (int i = blk*256 + tid; i < BH/4; i += NB*256) {
            int m = i >> 8, c4 = (i & 255) * 4;
            float4 a = make_float4(0,0,0,0), b = make_float4(0,0,0,0);
            #pragma unroll
            for (int s = 0; s < 4; ++s) {
                float4 pa = *(const float4*)(g_ppa[s] + (size_t)m*HH + c4);
                a.x += pa.x; a.y += pa.y; a.z += pa.z; a.w += pa.w;
            }
            #pragma unroll
            for (int s = 0; s < 8; ++s) {
                float4 pb = *(const float4*)(g_ppb[s] + (size_t)m*HH + c4);
                b.x += pb.x; b.y += pb.y; b.z += pb.z; b.w += pb.w;
            }
            *(float4*)(g_cat1 + (size_t)m*K1A + FEAT + c4) =
                make_float4(a.x*b.x, a.y*b.y, a.z*b.z, a.w*b.w);
        }
        for (int i = blk*256 + tid; i < BB*FEAT/4; i += NB*256) {
            int m = i / 144, c4 = (i % 144) * 4;
            *(float4*)(g_cat1 + (size_t)m*K1A + c4) = *(const float4*)(Xt + (size_t)m*FEAT + c4);
        }
        grid_sync(gen);

        // ---- P3: z1 partials: cat1 @ W1^T, K=1600, 32nt x 4sp {13,13,12,12}ch ----
        if (blk < 128) {
            int nt = blk >> 2, sp = blk & 3;
            int kbeg = (sp < 2) ? sp*416 : 832 + (sp-2)*384;
            int nch  = 13 - (sp >> 1);
            tc_gemm(g_cat1, K1A, g_W1 + (size_t)(nt*128)*K1A, K1A,
                    g_pz[sp] + nt*128, NG, kbeg, nch, smf);
        }
        grid_sync(gen);

        bool flag = (*(volatile float*)&g_flag > 0.5f);

        // ---- P3b: gates 1 epilogue ----
        for (int i = blk*256 + tid; i < BH/4; i += NB*256) {
            int m = i >> 8, c4 = (i & 255) * 4;
            float4 z[4];
            #pragma unroll
            for (int g = 0; g < 4; ++g) {
                int col = g*HH + c4;
                float4 sum = *(const float4*)(b1 + col);
                #pragma unroll
                for (int s = 0; s < 4; ++s) {
                    float4 p = *(const float4*)(g_pz[s] + (size_t)m*NG + col);
                    sum.x += p.x; sum.y += p.y; sum.z += p.z; sum.w += p.w;
                }
                z[g] = sum;
            }
            float s = g_s[m];
            size_t idx = (size_t)m*HH + c4;
            float4 co = *(const float4*)(g_c1 + idx);
            float cn0 = sigm(z[1].x)*co.x + sigm(z[0].x)*tanhf(z[2].x);
            float cn1 = sigm(z[1].y)*co.y + sigm(z[0].y)*tanhf(z[2].y);
            float cn2 = sigm(z[1].z)*co.z + sigm(z[0].z)*tanhf(z[2].z);
            float cn3 = sigm(z[1].w)*co.w + sigm(z[0].w)*tanhf(z[2].w);
            float hn0 = sigm(z[3].x)*tanhf(cn0);
            float hn1 = sigm(z[3].y)*tanhf(cn1);
            float hn2 = sigm(z[3].z)*tanhf(cn2);
            float hn3 = sigm(z[3].w)*tanhf(cn3);
            *(float4*)(g_cat2 + (size_t)m*K2A + c4) = make_float4(hn0*s, hn1*s, hn2*s, hn3*s);
            float r = 1.f - s;
            *(float4*)(g_h1 + idx) = make_float4(hn0*r, hn1*r, hn2*r, hn3*r);
            *(float4*)(g_c1 + idx) = make_float4(cn0*r, cn1*r, cn2*r, cn3*r);
            if (!flag)
                *(float4*)(out + ((size_t)m*SS + t)*HH + c4) = *(const float4*)(g_h2 + idx);
        }
        grid_sync(gen);

        if (flag) {
            // ---- P4: m2 partials, K=1024, 8nt x 8sp each side ----
            if (blk < 64) {
                int nt = blk >> 3, sp = blk & 7;
                tc_gemm(g_cat2, K2A, Wmx2 + (size_t)(nt*128)*HH, HH,
                        g_ppa[sp] + nt*128, HH, sp*128, 4, smf);
            } else if (blk < 128) {
                int q = blk - 64, nt = q >> 3, sp = q & 7;
                tc_gemm(g_h2, HH, Wmh2 + (size_t)(nt*128)*HH, HH,
                        g_ppb[sp] + nt*128, HH, sp*128, 4, smf);
            }
            grid_sync(gen);

            // ---- P5: m2 -> cat2[:,1024:] ----
            for (int i = blk*256 + tid; i < BH/4; i += NB*256) {
                int m = i >> 8, c4 = (i & 255) * 4;
                float4 a = make_float4(0,0,0,0), b = make_float4(0,0,0,0);
                #pragma unroll
                for (int s = 0; s < 8; ++s) {
                    float4 pa = *(const float4*)(g_ppa[s] + (size_t)m*HH + c4);
                    float4 pb = *(const float4*)(g_ppb[s] + (size_t)m*HH + c4);
                    a.x += pa.x; a.y += pa.y; a.z += pa.z; a.w += pa.w;
                    b.x += pb.x; b.y += pb.y; b.z += pb.z; b.w += pb.w;
                }
                *(float4*)(g_cat2 + (size_t)m*K2A + HH + c4) =
                    make_float4(a.x*b.x, a.y*b.y, a.z*b.z, a.w*b.w);
            }
            grid_sync(gen);

            // ---- P6: z2 partials: cat2 @ W2^T, K=2048, 32nt x 4sp x 16ch ----
            if (blk < 128) {
                int nt = blk >> 2, sp = blk & 3;
                tc_gemm(g_cat2, K2A, g_W2 + (size_t)(nt*128)*K2A, K2A,
                        g_pz[sp] + nt*128, NG, sp*512, 16, smf);
            }
            grid_sync(gen);

            // ---- P6b: gates 2 epilogue ----
            for (int i = blk*256 + tid; i < BH/4; i += NB*256) {
                int m = i >> 8, c4 = (i & 255) * 4;
                float4 z[4];
                #pragma unroll
                for (int g = 0; g < 4; ++g) {
                    int col = g*HH + c4;
                    float4 sum = *(const float4*)(b2 + col);
                    #pragma unroll
                    for (int s = 0; s < 4; ++s) {
                        float4 p = *(const float4*)(g_pz[s] + (size_t)m*NG + col);
                        sum.x += p.x; sum.y += p.y; sum.z += p.z; sum.w += p.w;
                    }
                    z[g] = sum;
                }
                size_t idx = (size_t)m*HH + c4;
                float4 co = *(const float4*)(g_c2 + idx);
                float cn0 = sigm(z[1].x)*co.x + sigm(z[0].x)*tanhf(z[2].x);
                float cn1 = sigm(z[1].y)*co.y + sigm(z[0].y)*tanhf(z[2].y);
                float cn2 = sigm(z[1].z)*co.z + sigm(z[0].z)*tanhf(z[2].z);
                float cn3 = sigm(z[1].w)*co.w + sigm(z[0].w)*tanhf(z[2].w);
                float hn0 = sigm(z[3].x)*tanhf(cn0);
                float hn1 = sigm(z[3].y)*tanhf(cn1);
                float hn2 = sigm(z[3].z)*tanhf(cn2);
                float hn3 = sigm(z[3].w)*tanhf(cn3);
                *(float4*)(g_c2 + idx) = make_float4(cn0, cn1, cn2, cn3);
                *(float4*)(g_h2 + idx) = make_float4(hn0, hn1, hn2, hn3);
                *(float4*)(out + ((size_t)m*SS + t)*HH + c4) = make_float4(hn0, hn1, hn2, hn3);
            }
            grid_sync(gen);
        }
    }

    size_t off1 = (size_t)BB*SS*HH;
    for (int i = blk*256 + tid; i < BH; i += NB*256) {
        out[off1 + i]      = g_h2[i];
        out[off1 + BH + i] = g_c2[i];
    }
}

extern "C" void kernel_launch(void* const* d_in, const int* in_sizes, int n_in,
                              void* d_out, int out_size)
{
    const int*   enc  = (const int*)d_in[0];
    const int*   encx = (const int*)d_in[1];
    const float* wemb = (const float*)d_in[2];
    const float* xemb = (const float*)d_in[3];
    const float* Wsi  = (const float*)d_in[4];
    const float* Wsh  = (const float*)d_in[5];
    const float* b_bd = (const float*)d_in[6];
    const float* vs   = (const float*)d_in[7];
    const float* Wmx1 = (const float*)d_in[8];
    const float* Wmh1 = (const float*)d_in[9];
    const float* Wih1 = (const float*)d_in[10];
    const float* Whh1 = (const float*)d_in[11];
    const float* b1   = (const float*)d_in[12];
    const float* Wmx2 = (const float*)d_in[13];
    const float* Wmh2 = (const float*)d_in[14];
    const float* Wih2 = (const float*)d_in[15];
    const float* Whh2 = (const float*)d_in[16];
    const float* b2   = (const float*)d_in[17];
    float* out = (float*)d_out;
    size_t off1 = (size_t)BB*SS*HH;
    float* flags_ptr = out + off1 + 2*(size_t)BH;

    static int smem_set = 0;
    if (!smem_set) {
        cudaFuncSetAttribute(main_kernel, cudaFuncAttributeMaxDynamicSharedMemorySize,
                             SMEM_DYN);
        smem_set = 1;
    }

    prep_kernel  <<<7, 256>>>(Wsi, Wsh, b_bd, vs);
    prep2_kernel <<<4096, 256>>>(Wih1, Whh1, Wih2, Whh2);
    zero_kernel  <<<512, 256>>>();
    gather_kernel<<<2048, 256>>>(enc, encx, wemb, xemb);
    main_kernel  <<<NB, 256, SMEM_DYN>>>(Wmx1, Wmh1, b1, Wmx2, Wmh2, b2,
                                         out, flags_ptr);
}